// round 1
// baseline (speedup 1.0000x reference)
#include <cuda_runtime.h>
#include <cstdint>

#define NNODE 10000
#define BNUM  4
#define DDIM  128
#define ECAP  262144
#define ND    (NNODE*DDIM)
#define SLOPE 0.01f

// ---------------- scratch (device globals; no allocation) ----------------
__device__ float g_x[BNUM*ND];      // layer activations (output of each layer)
__device__ float g_h[BNUM*ND];      // per-layer hidden h
__device__ float g_asrc[BNUM*NNODE];
__device__ float g_adst[BNUM*NNODE];
__device__ int   g_offs[NNODE+1];
__device__ int   g_cur[NNODE];      // counts -> cursor
__device__ int   g_srcs[ECAP];
__device__ float g_wnsW[3*DDIM];
__device__ float g_bnsW[3*DDIM];
__device__ float g_semb[BNUM*DDIM];
__device__ float g_rs[BNUM];

// ---------------- f32x2 helpers ----------------
__device__ __forceinline__ unsigned long long pack2(float x, float y) {
    unsigned long long r;
    asm("mov.b64 %0, {%1, %2};" : "=l"(r) : "f"(x), "f"(y));
    return r;
}
__device__ __forceinline__ unsigned long long ffma2(unsigned long long a,
                                                    unsigned long long b,
                                                    unsigned long long c) {
    unsigned long long d;
    asm("fma.rn.f32x2 %0, %1, %2, %3;" : "=l"(d) : "l"(a), "l"(b), "l"(c));
    return d;
}
__device__ __forceinline__ float2 unpack2(unsigned long long v) {
    float2 f;
    asm("mov.b64 {%0, %1}, %2;" : "=f"(f.x), "=f"(f.y) : "l"(v));
    return f;
}

// ---------------- CSR build ----------------
__global__ void k_zero_cnt() {
    int i = blockIdx.x*blockDim.x + threadIdx.x;
    if (i < NNODE) g_cur[i] = 0;
}
__global__ void k_hist(const int* __restrict__ ei, int Etot) {
    int e = blockIdx.x*blockDim.x + threadIdx.x;
    if (e < Etot) atomicAdd(&g_cur[ei[Etot + e]], 1);
}
__global__ void k_scan(int Etot) {
    __shared__ int sh[1024];
    const int ITEMS = 10;   // ceil(10000/1024)
    int t = threadIdx.x;
    int base = t*ITEMS;
    int loc[ITEMS]; int sum = 0;
#pragma unroll
    for (int i = 0; i < ITEMS; i++) {
        int idx = base + i;
        int v = (idx < NNODE) ? g_cur[idx] : 0;
        loc[i] = sum; sum += v;
    }
    sh[t] = sum; __syncthreads();
    for (int off = 1; off < 1024; off <<= 1) {
        int v = (t >= off) ? sh[t-off] : 0;
        __syncthreads();
        sh[t] += v;
        __syncthreads();
    }
    int pre = t ? sh[t-1] : 0;
#pragma unroll
    for (int i = 0; i < ITEMS; i++) {
        int idx = base + i;
        if (idx < NNODE) { int o = pre + loc[i]; g_offs[idx] = o; g_cur[idx] = o; }
    }
    if (t == 1023) g_offs[NNODE] = sh[1023];
}
__global__ void k_scatter(const int* __restrict__ ei, int Etot) {
    int e = blockIdx.x*blockDim.x + threadIdx.x;
    if (e < Etot) {
        int d = ei[Etot + e];
        int pos = atomicAdd(&g_cur[d], 1);
        g_srcs[pos] = ei[e];
    }
}

// ---------------- precompute WnsW / bnsW ----------------
__global__ void k_prep(const float* __restrict__ W, const float* __restrict__ Wns,
                       const float* __restrict__ bns) {
    int l = blockIdx.x, c = threadIdx.x;
    const float* Wl = W + l*DDIM*DDIM;
    float aw = 0.f, ab = 0.f;
    for (int k = 0; k < DDIM; k++) {
        float w = Wl[k*DDIM + c];
        aw += Wns[l*DDIM + k]*w;
        ab += bns[l*DDIM + k]*w;
    }
    g_wnsW[l*DDIM + c] = aw;
    g_bnsW[l*DDIM + c] = ab;
}

// ---------------- fused GEMM (64x128 tile, f32x2) ----------------
// MODE 0: h = x@W (+ state*WnsW + bnsW), plus a_src/a_dst epilogue
// MODE 1: out[b,n] = rs[b] + sum_d relu((x@W2)[d]+b2[d])*W3[128+d]
#define XST 76  // padded stride: conflict-free transposed stores & aligned f4 reads
template<int MODE>
__global__ void k_gemm(const float* __restrict__ xext, long bstride,
                       const float* __restrict__ W,
                       const float* __restrict__ state,
                       const float* __restrict__ attS, const float* __restrict__ attD,
                       int layer,
                       const float* __restrict__ b2, const float* __restrict__ W3,
                       float* __restrict__ out) {
    __shared__ float xsT[32][XST];
    __shared__ float ws[32][DDIM];
    const int tid = threadIdx.x;
    const int tx = tid & 31, ty = tid >> 5;
    const int b = blockIdx.y;
    const int rowbase = blockIdx.x * 64;
    const float* xp = xext ? xext : g_x;
    const size_t xboff = (size_t)b * (size_t)bstride;

    unsigned long long acc[4][4];
#pragma unroll
    for (int rp = 0; rp < 4; rp++)
#pragma unroll
        for (int c = 0; c < 4; c++) acc[rp][c] = 0ull;

    for (int kc = 0; kc < 4; ++kc) {
#pragma unroll
        for (int v = tid; v < 512; v += 256) {
            int r = v >> 3, kq = v & 7;
            int rowc = rowbase + r; rowc = rowc < NNODE ? rowc : NNODE-1;
            const float4 xv = *(const float4*)(xp + xboff + (size_t)rowc*DDIM + kc*32 + kq*4);
            int k0 = kq*4;
            xsT[k0+0][r] = xv.x; xsT[k0+1][r] = xv.y;
            xsT[k0+2][r] = xv.z; xsT[k0+3][r] = xv.w;
        }
#pragma unroll
        for (int v = tid; v < 1024; v += 256) {
            int kk = v >> 5, cq = v & 31;
            *(float4*)&ws[kk][cq*4] = *(const float4*)(W + (size_t)(kc*32+kk)*DDIM + cq*4);
        }
        __syncthreads();
#pragma unroll
        for (int kk = 0; kk < 32; ++kk) {
            float4 wv = *(const float4*)&ws[kk][tx*4];
            float4 a0 = *(const float4*)&xsT[kk][ty*8];
            float4 a1 = *(const float4*)&xsT[kk][ty*8+4];
            unsigned long long ar[4] = {pack2(a0.x,a0.y), pack2(a0.z,a0.w),
                                        pack2(a1.x,a1.y), pack2(a1.z,a1.w)};
            unsigned long long wd[4] = {pack2(wv.x,wv.x), pack2(wv.y,wv.y),
                                        pack2(wv.z,wv.z), pack2(wv.w,wv.w)};
#pragma unroll
            for (int rp = 0; rp < 4; rp++)
#pragma unroll
                for (int c = 0; c < 4; c++)
                    acc[rp][c] = ffma2(ar[rp], wd[c], acc[rp][c]);
        }
        __syncthreads();
    }

    float2 A[4][4];
#pragma unroll
    for (int rp = 0; rp < 4; rp++)
#pragma unroll
        for (int c = 0; c < 4; c++) A[rp][c] = unpack2(acc[rp][c]);

    const int r0 = rowbase + ty*8;
    const int lane = tx;

    if (MODE == 0) {
        float st[8];
#pragma unroll
        for (int i = 0; i < 8; i++) {
            int rr = r0 + i; rr = rr < NNODE ? rr : NNODE-1;
            st[i] = state[(size_t)b*NNODE + rr];
        }
        float4 wn = *(const float4*)(g_wnsW + layer*DDIM + tx*4);
        float4 bn = *(const float4*)(g_bnsW + layer*DDIM + tx*4);
        float wnc[4] = {wn.x, wn.y, wn.z, wn.w};
        float bnc[4] = {bn.x, bn.y, bn.z, bn.w};
#pragma unroll
        for (int rp = 0; rp < 4; rp++)
#pragma unroll
            for (int c = 0; c < 4; c++) {
                A[rp][c].x += st[2*rp]   * wnc[c] + bnc[c];
                A[rp][c].y += st[2*rp+1] * wnc[c] + bnc[c];
            }
        float4 as4 = *(const float4*)(attS + tx*4);
        float4 ad4 = *(const float4*)(attD + tx*4);
        float asc[4] = {as4.x, as4.y, as4.z, as4.w};
        float adc[4] = {ad4.x, ad4.y, ad4.z, ad4.w};
        float asr[8], ads[8];
#pragma unroll
        for (int i = 0; i < 8; i++) { asr[i] = 0.f; ads[i] = 0.f; }
#pragma unroll
        for (int rp = 0; rp < 4; rp++)
#pragma unroll
            for (int c = 0; c < 4; c++) {
                asr[2*rp]   += A[rp][c].x * asc[c];
                asr[2*rp+1] += A[rp][c].y * asc[c];
                ads[2*rp]   += A[rp][c].x * adc[c];
                ads[2*rp+1] += A[rp][c].y * adc[c];
            }
#pragma unroll
        for (int off = 16; off > 0; off >>= 1)
#pragma unroll
            for (int i = 0; i < 8; i++) {
                asr[i] += __shfl_xor_sync(0xffffffffu, asr[i], off);
                ads[i] += __shfl_xor_sync(0xffffffffu, ads[i], off);
            }
        if (lane == 0) {
#pragma unroll
            for (int i = 0; i < 8; i++) {
                int row = r0 + i;
                if (row < NNODE) {
                    g_asrc[(size_t)b*NNODE + row] = asr[i];
                    g_adst[(size_t)b*NNODE + row] = ads[i];
                }
            }
        }
        float* hb = g_h + (size_t)b*ND;
#pragma unroll
        for (int rp = 0; rp < 4; rp++) {
            int re = r0 + 2*rp, ro = re + 1;
            float4 ve = {A[rp][0].x, A[rp][1].x, A[rp][2].x, A[rp][3].x};
            float4 vo = {A[rp][0].y, A[rp][1].y, A[rp][2].y, A[rp][3].y};
            if (re < NNODE) *(float4*)(hb + (size_t)re*DDIM + tx*4) = ve;
            if (ro < NNODE) *(float4*)(hb + (size_t)ro*DDIM + tx*4) = vo;
        }
    } else {
        float4 b2v = *(const float4*)(b2 + tx*4);
        float4 w3v = *(const float4*)(W3 + DDIM + tx*4);
        float b2c[4] = {b2v.x, b2v.y, b2v.z, b2v.w};
        float w3c[4] = {w3v.x, w3v.y, w3v.z, w3v.w};
        float ra[8];
#pragma unroll
        for (int i = 0; i < 8; i++) ra[i] = 0.f;
#pragma unroll
        for (int rp = 0; rp < 4; rp++)
#pragma unroll
            for (int c = 0; c < 4; c++) {
                float vx = fmaxf(A[rp][c].x + b2c[c], 0.f);
                float vy = fmaxf(A[rp][c].y + b2c[c], 0.f);
                ra[2*rp]   += vx * w3c[c];
                ra[2*rp+1] += vy * w3c[c];
            }
#pragma unroll
        for (int off = 16; off > 0; off >>= 1)
#pragma unroll
            for (int i = 0; i < 8; i++)
                ra[i] += __shfl_xor_sync(0xffffffffu, ra[i], off);
        if (lane == 0) {
            float rsb = g_rs[b];
#pragma unroll
            for (int i = 0; i < 8; i++) {
                int row = r0 + i;
                if (row < NNODE) out[(size_t)b*NNODE + row] = rsb + ra[i];
            }
        }
    }
}

// ---------------- edge softmax + aggregate (one warp per (dst,b)) ----------------
__global__ void k_edge(const float* __restrict__ bias) {
    int gw = (blockIdx.x*blockDim.x + threadIdx.x) >> 5;
    int lane = threadIdx.x & 31;
    if (gw >= NNODE*BNUM) return;
    int n = gw % NNODE;
    int b = gw / NNODE;
    int e0 = g_offs[n], e1 = g_offs[n+1];
    float adst = g_adst[(size_t)b*NNODE + n];
    const float* asr = g_asrc + (size_t)b*NNODE;
    const float4* hb = (const float4*)(g_h + (size_t)b*ND);
    float4 acc = {0.f, 0.f, 0.f, 0.f};
    float m = -1e30f, s = 0.f;
    for (int e = e0; e < e1; ++e) {
        int sv = g_srcs[e];
        float ae = asr[sv] + adst;
        ae = ae > 0.f ? ae : SLOPE*ae;
        float mn = fmaxf(m, ae);
        float corr = __expf(m - mn);
        float p = __expf(ae - mn);
        s = s*corr + p;
        float4 hv = hb[(size_t)sv*32 + lane];
        acc.x = acc.x*corr + p*hv.x;
        acc.y = acc.y*corr + p*hv.y;
        acc.z = acc.z*corr + p*hv.z;
        acc.w = acc.w*corr + p*hv.w;
        m = mn;
    }
    float inv = 1.f/s;
    float4 bi = ((const float4*)bias)[lane];
    float4 o;
    o.x = fmaxf(acc.x*inv + bi.x, 0.f);
    o.y = fmaxf(acc.y*inv + bi.y, 0.f);
    o.z = fmaxf(acc.z*inv + bi.z, 0.f);
    o.w = fmaxf(acc.w*inv + bi.w, 0.f);
    ((float4*)(g_x + (size_t)b*ND))[(size_t)n*32 + lane] = o;
}

// ---------------- final head ----------------
__global__ void k_zero_semb() { g_semb[threadIdx.x] = 0.f; }

__global__ void k_reduce() {
    int b = blockIdx.y;
    int r0 = blockIdx.x * 250;
    int r1 = r0 + 250; if (r1 > NNODE) r1 = NNODE;
    int col = threadIdx.x & 127;
    int half = threadIdx.x >> 7;
    float acc = 0.f;
    const float* xb = g_x + (size_t)b*ND;
    for (int r = r0 + half; r < r1; r += 2) acc += xb[(size_t)r*DDIM + col];
    __shared__ float sh[256];
    sh[threadIdx.x] = acc; __syncthreads();
    if (half == 0) atomicAdd(&g_semb[b*DDIM + col], sh[col] + sh[col+128]);
}

__global__ void k_beta(const float* __restrict__ W1, const float* __restrict__ b1,
                       const float* __restrict__ W3, const float* __restrict__ b3) {
    int b = blockIdx.x, d = threadIdx.x;
    float acc = b1[d];
    for (int k = 0; k < DDIM; k++) acc += g_semb[b*DDIM + k] * W1[k*DDIM + d];
    float v = fmaxf(acc, 0.f) * W3[d];
    __shared__ float sh[DDIM];
    sh[d] = v; __syncthreads();
    for (int off = 64; off > 0; off >>= 1) {
        if (d < off) sh[d] += sh[d+off];
        __syncthreads();
    }
    if (d == 0) g_rs[b] = sh[0] + b3[0];
}

// ---------------- launch ----------------
extern "C" void kernel_launch(void* const* d_in, const int* in_sizes, int n_in,
                              void* d_out, int out_size) {
    const float* state = (const float*)d_in[0];
    const float* struc = (const float*)d_in[1];
    const int*   ei    = (const int*)d_in[2];
    const float* gatW  = (const float*)d_in[3];
    const float* attS  = (const float*)d_in[4];
    const float* attD  = (const float*)d_in[5];
    const float* Wns   = (const float*)d_in[6];
    const float* bns   = (const float*)d_in[7];
    const float* bias  = (const float*)d_in[8];
    const float* W1    = (const float*)d_in[9];
    const float* b1    = (const float*)d_in[10];
    const float* W2    = (const float*)d_in[11];
    const float* b2    = (const float*)d_in[12];
    const float* W3    = (const float*)d_in[13];
    const float* b3    = (const float*)d_in[14];
    float* out = (float*)d_out;
    int Etot = in_sizes[2] / 2;

    // CSR build (counting sort by dst)
    k_zero_cnt<<<(NNODE+255)/256, 256>>>();
    k_hist<<<(Etot+255)/256, 256>>>(ei, Etot);
    k_scan<<<1, 1024>>>(Etot);
    k_scatter<<<(Etot+255)/256, 256>>>(ei, Etot);
    k_prep<<<3, 128>>>(gatW, Wns, bns);

    dim3 ggrid((NNODE + 63)/64, BNUM);
    for (int l = 0; l < 3; l++) {
        const float* xe = (l == 0) ? struc : nullptr;
        long bs = (l == 0) ? 0L : (long)ND;
        k_gemm<0><<<ggrid, 256>>>(xe, bs, gatW + (size_t)l*DDIM*DDIM, state,
                                  attS + l*DDIM, attD + l*DDIM, l,
                                  nullptr, nullptr, nullptr);
        k_edge<<<(NNODE*BNUM*32)/256, 256>>>(bias + l*DDIM);
    }

    k_zero_semb<<<1, 512>>>();
    k_reduce<<<dim3(40, BNUM), 256>>>();
    k_beta<<<BNUM, 128>>>(W1, b1, W3, b3);
    k_gemm<1><<<ggrid, 256>>>(nullptr, (long)ND, W2, state,
                              nullptr, nullptr, 0, b2, W3, out);
}

// round 2
// speedup vs baseline: 1.0015x; 1.0015x over previous
#include <cuda_runtime.h>
#include <cstdint>

#define NNODE 10000
#define BNUM  4
#define DDIM  128
#define ECAP  262144
#define ND    (NNODE*DDIM)
#define SLOPE 0.01f

// ---------------- scratch (device globals; no allocation) ----------------
__device__ float g_x[BNUM*ND];      // layer activations (output of each layer)
__device__ float g_h[BNUM*ND];      // per-layer hidden h
__device__ float g_asrc[BNUM*NNODE];
__device__ float g_adst[BNUM*NNODE];
__device__ int   g_offs[NNODE+1];
__device__ int   g_cur[NNODE];      // counts -> cursor
__device__ int   g_srcs[ECAP];
__device__ float g_wnsW[3*DDIM];
__device__ float g_bnsW[3*DDIM];
__device__ float g_semb[BNUM*DDIM];
__device__ float g_rs[BNUM];

// ---------------- f32x2 helpers ----------------
__device__ __forceinline__ unsigned long long pack2(float x, float y) {
    unsigned long long r;
    asm("mov.b64 %0, {%1, %2};" : "=l"(r) : "f"(x), "f"(y));
    return r;
}
__device__ __forceinline__ unsigned long long ffma2(unsigned long long a,
                                                    unsigned long long b,
                                                    unsigned long long c) {
    unsigned long long d;
    asm("fma.rn.f32x2 %0, %1, %2, %3;" : "=l"(d) : "l"(a), "l"(b), "l"(c));
    return d;
}
__device__ __forceinline__ float2 unpack2(unsigned long long v) {
    float2 f;
    asm("mov.b64 {%0, %1}, %2;" : "=f"(f.x), "=f"(f.y) : "l"(v));
    return f;
}

// ---------------- CSR build ----------------
__global__ void k_zero_cnt() {
    int i = blockIdx.x*blockDim.x + threadIdx.x;
    if (i < NNODE) g_cur[i] = 0;
}
__global__ void k_hist(const int* __restrict__ ei, int Etot) {
    int e = blockIdx.x*blockDim.x + threadIdx.x;
    if (e < Etot) atomicAdd(&g_cur[ei[Etot + e]], 1);
}
__global__ void k_scan(int Etot) {
    __shared__ int sh[1024];
    const int ITEMS = 10;   // ceil(10000/1024)
    int t = threadIdx.x;
    int base = t*ITEMS;
    int loc[ITEMS]; int sum = 0;
#pragma unroll
    for (int i = 0; i < ITEMS; i++) {
        int idx = base + i;
        int v = (idx < NNODE) ? g_cur[idx] : 0;
        loc[i] = sum; sum += v;
    }
    sh[t] = sum; __syncthreads();
    for (int off = 1; off < 1024; off <<= 1) {
        int v = (t >= off) ? sh[t-off] : 0;
        __syncthreads();
        sh[t] += v;
        __syncthreads();
    }
    int pre = t ? sh[t-1] : 0;
#pragma unroll
    for (int i = 0; i < ITEMS; i++) {
        int idx = base + i;
        if (idx < NNODE) { int o = pre + loc[i]; g_offs[idx] = o; g_cur[idx] = o; }
    }
    if (t == 1023) g_offs[NNODE] = sh[1023];
}
__global__ void k_scatter(const int* __restrict__ ei, int Etot) {
    int e = blockIdx.x*blockDim.x + threadIdx.x;
    if (e < Etot) {
        int d = ei[Etot + e];
        int pos = atomicAdd(&g_cur[d], 1);
        g_srcs[pos] = ei[e];
    }
}

// ---------------- precompute WnsW / bnsW ----------------
__global__ void k_prep(const float* __restrict__ W, const float* __restrict__ Wns,
                       const float* __restrict__ bns) {
    int l = blockIdx.x, c = threadIdx.x;
    const float* Wl = W + l*DDIM*DDIM;
    float aw = 0.f, ab = 0.f;
    for (int k = 0; k < DDIM; k++) {
        float w = Wl[k*DDIM + c];
        aw += Wns[l*DDIM + k]*w;
        ab += bns[l*DDIM + k]*w;
    }
    g_wnsW[l*DDIM + c] = aw;
    g_bnsW[l*DDIM + c] = ab;
}

// ---------------- fused GEMM (64x128 tile, f32x2) ----------------
// MODE 0: h = x@W (+ state*WnsW + bnsW), plus a_src/a_dst epilogue
// MODE 1: out[b,n] = rs[b] + sum_d relu((x@W2)[d]+b2[d])*W3[128+d]
#define XST 76  // padded stride: conflict-free transposed stores & aligned f4 reads
template<int MODE>
__global__ void k_gemm(const float* __restrict__ xext, long bstride,
                       const float* __restrict__ W,
                       const float* __restrict__ state,
                       const float* __restrict__ attS, const float* __restrict__ attD,
                       int layer,
                       const float* __restrict__ b2, const float* __restrict__ W3,
                       float* __restrict__ out) {
    __shared__ float xsT[32][XST];
    __shared__ float ws[32][DDIM];
    const int tid = threadIdx.x;
    const int tx = tid & 31, ty = tid >> 5;
    const int b = blockIdx.y;
    const int rowbase = blockIdx.x * 64;
    const float* xp = xext ? xext : g_x;
    const size_t xboff = (size_t)b * (size_t)bstride;

    unsigned long long acc[4][4];
#pragma unroll
    for (int rp = 0; rp < 4; rp++)
#pragma unroll
        for (int c = 0; c < 4; c++) acc[rp][c] = 0ull;

    for (int kc = 0; kc < 4; ++kc) {
#pragma unroll
        for (int v = tid; v < 512; v += 256) {
            int r = v >> 3, kq = v & 7;
            int rowc = rowbase + r; rowc = rowc < NNODE ? rowc : NNODE-1;
            const float4 xv = *(const float4*)(xp + xboff + (size_t)rowc*DDIM + kc*32 + kq*4);
            int k0 = kq*4;
            xsT[k0+0][r] = xv.x; xsT[k0+1][r] = xv.y;
            xsT[k0+2][r] = xv.z; xsT[k0+3][r] = xv.w;
        }
#pragma unroll
        for (int v = tid; v < 1024; v += 256) {
            int kk = v >> 5, cq = v & 31;
            *(float4*)&ws[kk][cq*4] = *(const float4*)(W + (size_t)(kc*32+kk)*DDIM + cq*4);
        }
        __syncthreads();
#pragma unroll
        for (int kk = 0; kk < 32; ++kk) {
            float4 wv = *(const float4*)&ws[kk][tx*4];
            float4 a0 = *(const float4*)&xsT[kk][ty*8];
            float4 a1 = *(const float4*)&xsT[kk][ty*8+4];
            unsigned long long ar[4] = {pack2(a0.x,a0.y), pack2(a0.z,a0.w),
                                        pack2(a1.x,a1.y), pack2(a1.z,a1.w)};
            unsigned long long wd[4] = {pack2(wv.x,wv.x), pack2(wv.y,wv.y),
                                        pack2(wv.z,wv.z), pack2(wv.w,wv.w)};
#pragma unroll
            for (int rp = 0; rp < 4; rp++)
#pragma unroll
                for (int c = 0; c < 4; c++)
                    acc[rp][c] = ffma2(ar[rp], wd[c], acc[rp][c]);
        }
        __syncthreads();
    }

    float2 A[4][4];
#pragma unroll
    for (int rp = 0; rp < 4; rp++)
#pragma unroll
        for (int c = 0; c < 4; c++) A[rp][c] = unpack2(acc[rp][c]);

    const int r0 = rowbase + ty*8;
    const int lane = tx;

    if (MODE == 0) {
        float st[8];
#pragma unroll
        for (int i = 0; i < 8; i++) {
            int rr = r0 + i; rr = rr < NNODE ? rr : NNODE-1;
            st[i] = state[(size_t)b*NNODE + rr];
        }
        float4 wn = *(const float4*)(g_wnsW + layer*DDIM + tx*4);
        float4 bn = *(const float4*)(g_bnsW + layer*DDIM + tx*4);
        float wnc[4] = {wn.x, wn.y, wn.z, wn.w};
        float bnc[4] = {bn.x, bn.y, bn.z, bn.w};
#pragma unroll
        for (int rp = 0; rp < 4; rp++)
#pragma unroll
            for (int c = 0; c < 4; c++) {
                A[rp][c].x += st[2*rp]   * wnc[c] + bnc[c];
                A[rp][c].y += st[2*rp+1] * wnc[c] + bnc[c];
            }
        float4 as4 = *(const float4*)(attS + tx*4);
        float4 ad4 = *(const float4*)(attD + tx*4);
        float asc[4] = {as4.x, as4.y, as4.z, as4.w};
        float adc[4] = {ad4.x, ad4.y, ad4.z, ad4.w};
        float asr[8], ads[8];
#pragma unroll
        for (int i = 0; i < 8; i++) { asr[i] = 0.f; ads[i] = 0.f; }
#pragma unroll
        for (int rp = 0; rp < 4; rp++)
#pragma unroll
            for (int c = 0; c < 4; c++) {
                asr[2*rp]   += A[rp][c].x * asc[c];
                asr[2*rp+1] += A[rp][c].y * asc[c];
                ads[2*rp]   += A[rp][c].x * adc[c];
                ads[2*rp+1] += A[rp][c].y * adc[c];
            }
#pragma unroll
        for (int off = 16; off > 0; off >>= 1)
#pragma unroll
            for (int i = 0; i < 8; i++) {
                asr[i] += __shfl_xor_sync(0xffffffffu, asr[i], off);
                ads[i] += __shfl_xor_sync(0xffffffffu, ads[i], off);
            }
        if (lane == 0) {
#pragma unroll
            for (int i = 0; i < 8; i++) {
                int row = r0 + i;
                if (row < NNODE) {
                    g_asrc[(size_t)b*NNODE + row] = asr[i];
                    g_adst[(size_t)b*NNODE + row] = ads[i];
                }
            }
        }
        float* hb = g_h + (size_t)b*ND;
#pragma unroll
        for (int rp = 0; rp < 4; rp++) {
            int re = r0 + 2*rp, ro = re + 1;
            float4 ve = {A[rp][0].x, A[rp][1].x, A[rp][2].x, A[rp][3].x};
            float4 vo = {A[rp][0].y, A[rp][1].y, A[rp][2].y, A[rp][3].y};
            if (re < NNODE) *(float4*)(hb + (size_t)re*DDIM + tx*4) = ve;
            if (ro < NNODE) *(float4*)(hb + (size_t)ro*DDIM + tx*4) = vo;
        }
    } else {
        float4 b2v = *(const float4*)(b2 + tx*4);
        float4 w3v = *(const float4*)(W3 + DDIM + tx*4);
        float b2c[4] = {b2v.x, b2v.y, b2v.z, b2v.w};
        float w3c[4] = {w3v.x, w3v.y, w3v.z, w3v.w};
        float ra[8];
#pragma unroll
        for (int i = 0; i < 8; i++) ra[i] = 0.f;
#pragma unroll
        for (int rp = 0; rp < 4; rp++)
#pragma unroll
            for (int c = 0; c < 4; c++) {
                float vx = fmaxf(A[rp][c].x + b2c[c], 0.f);
                float vy = fmaxf(A[rp][c].y + b2c[c], 0.f);
                ra[2*rp]   += vx * w3c[c];
                ra[2*rp+1] += vy * w3c[c];
            }
#pragma unroll
        for (int off = 16; off > 0; off >>= 1)
#pragma unroll
            for (int i = 0; i < 8; i++)
                ra[i] += __shfl_xor_sync(0xffffffffu, ra[i], off);
        if (lane == 0) {
            float rsb = g_rs[b];
#pragma unroll
            for (int i = 0; i < 8; i++) {
                int row = r0 + i;
                if (row < NNODE) out[(size_t)b*NNODE + row] = rsb + ra[i];
            }
        }
    }
}

// ---------------- edge softmax + aggregate (one warp per (dst,b)) ----------------
__global__ void k_edge(const float* __restrict__ bias) {
    int gw = (blockIdx.x*blockDim.x + threadIdx.x) >> 5;
    int lane = threadIdx.x & 31;
    if (gw >= NNODE*BNUM) return;
    int n = gw % NNODE;
    int b = gw / NNODE;
    int e0 = g_offs[n], e1 = g_offs[n+1];
    float adst = g_adst[(size_t)b*NNODE + n];
    const float* asr = g_asrc + (size_t)b*NNODE;
    const float4* hb = (const float4*)(g_h + (size_t)b*ND);
    float4 acc = {0.f, 0.f, 0.f, 0.f};
    float m = -1e30f, s = 0.f;
    for (int e = e0; e < e1; ++e) {
        int sv = g_srcs[e];
        float ae = asr[sv] + adst;
        ae = ae > 0.f ? ae : SLOPE*ae;
        float mn = fmaxf(m, ae);
        float corr = __expf(m - mn);
        float p = __expf(ae - mn);
        s = s*corr + p;
        float4 hv = hb[(size_t)sv*32 + lane];
        acc.x = acc.x*corr + p*hv.x;
        acc.y = acc.y*corr + p*hv.y;
        acc.z = acc.z*corr + p*hv.z;
        acc.w = acc.w*corr + p*hv.w;
        m = mn;
    }
    float inv = 1.f/s;
    float4 bi = ((const float4*)bias)[lane];
    float4 o;
    o.x = fmaxf(acc.x*inv + bi.x, 0.f);
    o.y = fmaxf(acc.y*inv + bi.y, 0.f);
    o.z = fmaxf(acc.z*inv + bi.z, 0.f);
    o.w = fmaxf(acc.w*inv + bi.w, 0.f);
    ((float4*)(g_x + (size_t)b*ND))[(size_t)n*32 + lane] = o;
}

// ---------------- final head ----------------
__global__ void k_zero_semb() { g_semb[threadIdx.x] = 0.f; }

__global__ void k_reduce() {
    int b = blockIdx.y;
    int r0 = blockIdx.x * 250;
    int r1 = r0 + 250; if (r1 > NNODE) r1 = NNODE;
    int col = threadIdx.x & 127;
    int half = threadIdx.x >> 7;
    float acc = 0.f;
    const float* xb = g_x + (size_t)b*ND;
    for (int r = r0 + half; r < r1; r += 2) acc += xb[(size_t)r*DDIM + col];
    __shared__ float sh[256];
    sh[threadIdx.x] = acc; __syncthreads();
    if (half == 0) atomicAdd(&g_semb[b*DDIM + col], sh[col] + sh[col+128]);
}

__global__ void k_beta(const float* __restrict__ W1, const float* __restrict__ b1,
                       const float* __restrict__ W3, const float* __restrict__ b3) {
    int b = blockIdx.x, d = threadIdx.x;
    float acc = b1[d];
    for (int k = 0; k < DDIM; k++) acc += g_semb[b*DDIM + k] * W1[k*DDIM + d];
    float v = fmaxf(acc, 0.f) * W3[d];
    __shared__ float sh[DDIM];
    sh[d] = v; __syncthreads();
    for (int off = 64; off > 0; off >>= 1) {
        if (d < off) sh[d] += sh[d+off];
        __syncthreads();
    }
    if (d == 0) g_rs[b] = sh[0] + b3[0];
}

// ---------------- launch ----------------
extern "C" void kernel_launch(void* const* d_in, const int* in_sizes, int n_in,
                              void* d_out, int out_size) {
    const float* state = (const float*)d_in[0];
    const float* struc = (const float*)d_in[1];
    const int*   ei    = (const int*)d_in[2];
    const float* gatW  = (const float*)d_in[3];
    const float* attS  = (const float*)d_in[4];
    const float* attD  = (const float*)d_in[5];
    const float* Wns   = (const float*)d_in[6];
    const float* bns   = (const float*)d_in[7];
    const float* bias  = (const float*)d_in[8];
    const float* W1    = (const float*)d_in[9];
    const float* b1    = (const float*)d_in[10];
    const float* W2    = (const float*)d_in[11];
    const float* b2    = (const float*)d_in[12];
    const float* W3    = (const float*)d_in[13];
    const float* b3    = (const float*)d_in[14];
    float* out = (float*)d_out;
    int Etot = in_sizes[2] / 2;

    // CSR build (counting sort by dst)
    k_zero_cnt<<<(NNODE+255)/256, 256>>>();
    k_hist<<<(Etot+255)/256, 256>>>(ei, Etot);
    k_scan<<<1, 1024>>>(Etot);
    k_scatter<<<(Etot+255)/256, 256>>>(ei, Etot);
    k_prep<<<3, 128>>>(gatW, Wns, bns);

    dim3 ggrid((NNODE + 63)/64, BNUM);
    for (int l = 0; l < 3; l++) {
        const float* xe = (l == 0) ? struc : nullptr;
        long bs = (l == 0) ? 0L : (long)ND;
        k_gemm<0><<<ggrid, 256>>>(xe, bs, gatW + (size_t)l*DDIM*DDIM, state,
                                  attS + l*DDIM, attD + l*DDIM, l,
                                  nullptr, nullptr, nullptr);
        k_edge<<<(NNODE*BNUM*32)/256, 256>>>(bias + l*DDIM);
    }

    k_zero_semb<<<1, 512>>>();
    k_reduce<<<dim3(40, BNUM), 256>>>();
    k_beta<<<BNUM, 128>>>(W1, b1, W3, b3);
    k_gemm<1><<<ggrid, 256>>>(nullptr, (long)ND, W2, state,
                              nullptr, nullptr, 0, b2, W3, out);
}